// round 9
// baseline (speedup 1.0000x reference)
#include <cuda_runtime.h>
#include <cstdint>

// ---------------- problem constants ----------------
#define VN     512          // graph nodes
#define LN     13           // sequence length
#define BB     64           // batch
#define CN     32           // in channels
#define NC     (BB*CN)      // 2048
#define MCOLS  (NC*LN)      // 26624
#define CO     64           // out channels
#define CCAT   224          // 7*CN
#define KDIM   VN           // contraction dim of propagation
#define NM     425984       // B*V*L (epilogue N; = 1664*256)
#define VLN    6656         // V*L (= 26*256)
#define CBLK   832          // per-c column block in Xt = BB*LN

// propagation tiling
#define BM   128
#define BNT  104            // 8 n * 13 l, single c per tile
#define BK   16
#define BELE (BK*BNT)       // 1664 B elements per chunk

// scratch
__device__ float g_Xt[(size_t)VN * MCOLS];        // Xt[v][c*832 + n*13 + l]
__device__ float g_H [(size_t)CCAT * NM];         // H[j*32+c][n*6656 + v*13 + l]
__device__ float g_S2[3 * (size_t)VN * VN];       // squared supports A*A

// ---------------- packed f32x2 helpers ----------------
__device__ __forceinline__ unsigned long long pack_dup(float b) {
    unsigned long long r;
    asm("mov.b64 %0, {%1, %1};" : "=l"(r) : "f"(b));
    return r;
}
__device__ __forceinline__ void fma2(unsigned long long &d,
                                     unsigned long long a,
                                     unsigned long long b) {
    asm("fma.rn.f32x2 %0, %1, %2, %0;" : "+l"(d) : "l"(a), "l"(b));
}
__device__ __forceinline__ float lo32(unsigned long long v) {
    return __uint_as_float((unsigned)(v & 0xffffffffull));
}
__device__ __forceinline__ float hi32(unsigned long long v) {
    return __uint_as_float((unsigned)(v >> 32));
}

// ---------------- 1) transpose x[n,c,v,l] -> Xt[v][(c,n,l)] + H rows 0..31 --
__global__ void transpose_kernel(const float* __restrict__ x) {
    int v = blockIdx.x;
    int q = blockIdx.y * blockDim.x + threadIdx.x;  // 0..2047, c outer / n inner
    int c = q >> 6;
    int n = q & 63;
    const float* src = x + ((size_t)(n * CN + c)) * (VN * LN) + v * LN;
    float* dst1 = g_Xt + (size_t)v * MCOLS + c * CBLK + n * LN;
    float* dst2 = g_H  + (size_t)c * NM + (size_t)n * VLN + v * LN;
#pragma unroll
    for (int l = 0; l < LN; ++l) {
        float val = src[l];
        dst1[l] = val;
        dst2[l] = val;
    }
}

// ---------------- 1b) square supports: S2 = A * A ---------------------------
__global__ void __launch_bounds__(256) square_support(
    const float* __restrict__ A0, const float* __restrict__ A1,
    const float* __restrict__ A2)
{
    const int z = blockIdx.z;
    const float* __restrict__ A = (z == 0) ? A0 : ((z == 1) ? A1 : A2);
    float* __restrict__ C = g_S2 + (size_t)z * VN * VN;

    const int i0 = blockIdx.y * 64;
    const int j0 = blockIdx.x * 64;

    __shared__ __align__(16) float As[64][16];
    __shared__ __align__(16) float Bs[16][64];

    const int tid = threadIdx.x;
    const int ty = tid >> 4;
    const int tx = tid & 15;
    const int ar = tid >> 2;
    const int ac = (tid & 3) * 4;
    const int br = tid >> 4;
    const int bc = (tid & 15) * 4;

    float acc[4][4];
#pragma unroll
    for (int i = 0; i < 4; ++i)
#pragma unroll
        for (int j = 0; j < 4; ++j) acc[i][j] = 0.f;

    for (int k0 = 0; k0 < VN; k0 += 16) {
        float4 av = *(const float4*)(A + (size_t)(i0 + ar) * VN + k0 + ac);
        float4 bv = *(const float4*)(A + (size_t)(k0 + br) * VN + j0 + bc);
        __syncthreads();
        *(float4*)&As[ar][ac] = av;
        *(float4*)&Bs[br][bc] = bv;
        __syncthreads();
#pragma unroll
        for (int k = 0; k < 16; ++k) {
            float a0 = As[ty * 4 + 0][k], a1 = As[ty * 4 + 1][k];
            float a2 = As[ty * 4 + 2][k], a3 = As[ty * 4 + 3][k];
            float4 b = *(const float4*)&Bs[k][tx * 4];
            acc[0][0] += a0 * b.x; acc[0][1] += a0 * b.y; acc[0][2] += a0 * b.z; acc[0][3] += a0 * b.w;
            acc[1][0] += a1 * b.x; acc[1][1] += a1 * b.y; acc[1][2] += a1 * b.z; acc[1][3] += a1 * b.w;
            acc[2][0] += a2 * b.x; acc[2][1] += a2 * b.y; acc[2][2] += a2 * b.z; acc[2][3] += a2 * b.w;
            acc[3][0] += a3 * b.x; acc[3][1] += a3 * b.y; acc[3][2] += a3 * b.z; acc[3][3] += a3 * b.w;
        }
    }
#pragma unroll
    for (int i = 0; i < 4; ++i) {
        float4 v = make_float4(acc[i][0], acc[i][1], acc[i][2], acc[i][3]);
        *(float4*)(C + (size_t)(i0 + ty * 4 + i) * VN + j0 + tx * 4) = v;
    }
}

// ---------------- 2) propagation SGEMM with coalesced H writes --------------
// C[w, m] = sum_v A[v,w] * Xt[v, m]; m = c*832 + n*13 + l.
// Tile: 128 w x 104 m (one c, 8 n, all l). 256 threads:
//   ty = tid>>3 (0..31) -> 4 consecutive w each;  tx = tid&7 -> one n, all 13 l.
// z=0..2: support_z (j=1+2z); z=3..5: S2_{z-3} (j=2+2(z-3)).
// Thread writes a contiguous 52-float run of g_H -> 13 STG.128.
__global__ void __launch_bounds__(256) prop_gemm(
    const float* __restrict__ A0, const float* __restrict__ A1,
    const float* __restrict__ A2)
{
    const int z = blockIdx.z;
    const float* __restrict__ A =
        (z == 0) ? A0 : (z == 1) ? A1 : (z == 2) ? A2
                  : (g_S2 + (size_t)(z - 3) * VN * VN);
    const int j = (z < 3) ? (1 + 2 * z) : (2 + 2 * (z - 3));

    const int w0 = blockIdx.y * BM;
    const int m0 = blockIdx.x * BNT;
    const int c  = blockIdx.x >> 3;          // 104*8 = 832 per c
    const int n0 = (blockIdx.x & 7) * 8;

    __shared__ __align__(16) float As[2][BK][BM];                    // 16 KB
    __shared__ __align__(16) unsigned long long Bsp[2][BK][BNT];     // 26.6 KB

    const int tid = threadIdx.x;
    const int lk = tid >> 5;   // A-load row 0..7 (and +8)
    const int lq = tid & 31;   // A-load float4 col
    const int ty = tid >> 3;   // 0..31 (w)
    const int tx = tid & 7;    // 0..7  (n)

    const float* Ag = A    + (size_t)lk * VN + w0 + lq * 4;
    const float* Bg = g_Xt + m0;

    unsigned long long acc[2][13];
#pragma unroll
    for (int i = 0; i < 2; ++i)
#pragma unroll
        for (int q = 0; q < 13; ++q) acc[i][q] = 0ull;

    // prologue: chunk 0 -> buffer 0
    {
        float4 a0 = *(const float4*)Ag;
        float4 a1 = *(const float4*)(Ag + 8 * VN);
        *(float4*)&As[0][lk    ][lq * 4] = a0;
        *(float4*)&As[0][lk + 8][lq * 4] = a1;
#pragma unroll
        for (int it = 0; it < 7; ++it) {
            int e = tid + it * 256;
            if (e < BELE) {
                int kr = e / BNT, cc = e - kr * BNT;
                Bsp[0][kr][cc] = pack_dup(Bg[(size_t)kr * MCOLS + cc]);
            }
        }
    }
    __syncthreads();

    int buf = 0;
#pragma unroll 1
    for (int kt = 0; kt < KDIM / BK; ++kt) {
        float4 na0, na1;
        float pb[7];
        const bool has_next = (kt < KDIM / BK - 1);
        if (has_next) {
            const float* Ap = Ag + (size_t)(kt + 1) * (BK * VN);
            const float* Bp = Bg + (size_t)(kt + 1) * (BK * MCOLS);
            na0 = *(const float4*)Ap;
            na1 = *(const float4*)(Ap + 8 * VN);
#pragma unroll
            for (int it = 0; it < 7; ++it) {
                int e = tid + it * 256;
                if (e < BELE) {
                    int kr = e / BNT, cc = e - kr * BNT;
                    pb[it] = Bp[(size_t)kr * MCOLS + cc];
                }
            }
        }
#pragma unroll
        for (int kk = 0; kk < BK; ++kk) {
            ulonglong2 a = *(const ulonglong2*)&As[buf][kk][ty * 4];
#pragma unroll
            for (int q = 0; q < 13; ++q) {
                unsigned long long b = Bsp[buf][kk][tx * 13 + q];
                fma2(acc[0][q], a.x, b);
                fma2(acc[1][q], a.y, b);
            }
        }
        if (has_next) {
            int nb = buf ^ 1;
            *(float4*)&As[nb][lk    ][lq * 4] = na0;
            *(float4*)&As[nb][lk + 8][lq * 4] = na1;
#pragma unroll
            for (int it = 0; it < 7; ++it) {
                int e = tid + it * 256;
                if (e < BELE) {
                    int kr = e / BNT, cc = e - kr * BNT;
                    Bsp[nb][kr][cc] = pack_dup(pb[it]);
                }
            }
        }
        __syncthreads();
        buf ^= 1;
    }

    // write-out: thread owns w = w0+ty*4..+3 (acc[i] lo/hi), n = n0+tx, l=0..12
    // -> 52 contiguous floats in g_H starting at row (j*32+c), col n*6656+(w0+ty*4)*13
    {
        const int n = n0 + tx;
        float* dst = g_H + (size_t)(j * CN + c) * NM
                         + (size_t)n * VLN + (size_t)(w0 + ty * 4) * LN;
#pragma unroll
        for (int t = 0; t < 13; ++t) {
            float e0, e1, e2, e3;
            {
                int p = 4 * t + 0, wl = p / 13, q = p - wl * 13;
                e0 = (wl & 1) ? hi32(acc[wl >> 1][q]) : lo32(acc[wl >> 1][q]);
            }
            {
                int p = 4 * t + 1, wl = p / 13, q = p - wl * 13;
                e1 = (wl & 1) ? hi32(acc[wl >> 1][q]) : lo32(acc[wl >> 1][q]);
            }
            {
                int p = 4 * t + 2, wl = p / 13, q = p - wl * 13;
                e2 = (wl & 1) ? hi32(acc[wl >> 1][q]) : lo32(acc[wl >> 1][q]);
            }
            {
                int p = 4 * t + 3, wl = p / 13, q = p - wl * 13;
                e3 = (wl & 1) ? hi32(acc[wl >> 1][q]) : lo32(acc[wl >> 1][q]);
            }
            *(float4*)(dst + 4 * t) = make_float4(e0, e1, e2, e3);
        }
    }
}

// ---------------- 3) epilogue skinny GEMM: out = W * H + b ------------------
#define EBK 8
__global__ void __launch_bounds__(256) mix_gemm(
    const float* __restrict__ Wm, const float* __restrict__ bias,
    float* __restrict__ out)
{
    const int m0 = blockIdx.x * 256;

    __shared__ __align__(16) float Ws[2][EBK][CO];
    __shared__ __align__(16) float Bs[2][EBK][256];

    const int tid = threadIdx.x;
    const int ty = tid >> 5;
    const int tx = tid & 31;
    const int lr = tid >> 5;
    const int lc = (tid & 31) * 4;
    const int wo_ = tid & 63;
    const int wk_ = tid >> 6;

    unsigned long long acc[4][8];
#pragma unroll
    for (int i = 0; i < 4; ++i)
#pragma unroll
        for (int jj = 0; jj < 8; ++jj) acc[i][jj] = 0ull;

    {
        float4 b0 = *(const float4*)(g_H + (size_t)lr * NM + m0 + lc);
        float4 b1 = *(const float4*)(g_H + (size_t)lr * NM + m0 + lc + 128);
        float w0v = Wm[wo_ * CCAT + wk_];
        float w1v = Wm[wo_ * CCAT + wk_ + 4];
        *(float4*)&Bs[0][lr][lc]       = b0;
        *(float4*)&Bs[0][lr][lc + 128] = b1;
        Ws[0][wk_][wo_]     = w0v;
        Ws[0][wk_ + 4][wo_] = w1v;
    }
    __syncthreads();

    int buf = 0;
#pragma unroll 1
    for (int kt = 0; kt < CCAT / EBK; ++kt) {
        float4 nb0, nb1;
        float nw0, nw1;
        const bool has_next = (kt < CCAT / EBK - 1);
        if (has_next) {
            int k0 = (kt + 1) * EBK;
            nb0 = *(const float4*)(g_H + (size_t)(k0 + lr) * NM + m0 + lc);
            nb1 = *(const float4*)(g_H + (size_t)(k0 + lr) * NM + m0 + lc + 128);
            nw0 = Wm[wo_ * CCAT + k0 + wk_];
            nw1 = Wm[wo_ * CCAT + k0 + wk_ + 4];
        }
#pragma unroll
        for (int kk = 0; kk < EBK; ++kk) {
            ulonglong2 a01 = *(const ulonglong2*)&Ws[buf][kk][ty * 4];
            ulonglong2 a23 = *(const ulonglong2*)&Ws[buf][kk][32 + ty * 4];
            float4 blo = *(const float4*)&Bs[buf][kk][tx * 4];
            float4 bhi = *(const float4*)&Bs[buf][kk][128 + tx * 4];
            unsigned long long av[4] = {a01.x, a01.y, a23.x, a23.y};
            unsigned long long bb[8];
            bb[0] = pack_dup(blo.x); bb[1] = pack_dup(blo.y);
            bb[2] = pack_dup(blo.z); bb[3] = pack_dup(blo.w);
            bb[4] = pack_dup(bhi.x); bb[5] = pack_dup(bhi.y);
            bb[6] = pack_dup(bhi.z); bb[7] = pack_dup(bhi.w);
#pragma unroll
            for (int i = 0; i < 4; ++i)
#pragma unroll
                for (int jj = 0; jj < 8; ++jj)
                    fma2(acc[i][jj], av[i], bb[jj]);
        }
        if (has_next) {
            int nb = buf ^ 1;
            *(float4*)&Bs[nb][lr][lc]       = nb0;
            *(float4*)&Bs[nb][lr][lc + 128] = nb1;
            Ws[nb][wk_][wo_]     = nw0;
            Ws[nb][wk_ + 4][wo_] = nw1;
        }
        __syncthreads();
        buf ^= 1;
    }

    const int n   = m0 / VLN;
    const int vl0 = m0 - n * VLN;
#pragma unroll
    for (int ia = 0; ia < 4; ++ia) {
        int o0 = ((ia >= 2) ? 32 : 0) + ty * 4 + (ia & 1) * 2;
        float blo = bias[o0], bhi = bias[o0 + 1];
        float* plo = out + ((size_t)n * CO + o0) * VLN + vl0 + tx * 4;
        float* phi = plo + VLN;
        float4 vlo0 = make_float4(lo32(acc[ia][0]) + blo, lo32(acc[ia][1]) + blo,
                                  lo32(acc[ia][2]) + blo, lo32(acc[ia][3]) + blo);
        float4 vlo1 = make_float4(lo32(acc[ia][4]) + blo, lo32(acc[ia][5]) + blo,
                                  lo32(acc[ia][6]) + blo, lo32(acc[ia][7]) + blo);
        float4 vhi0 = make_float4(hi32(acc[ia][0]) + bhi, hi32(acc[ia][1]) + bhi,
                                  hi32(acc[ia][2]) + bhi, hi32(acc[ia][3]) + bhi);
        float4 vhi1 = make_float4(hi32(acc[ia][4]) + bhi, hi32(acc[ia][5]) + bhi,
                                  hi32(acc[ia][6]) + bhi, hi32(acc[ia][7]) + bhi);
        *(float4*)(plo)       = vlo0;
        *(float4*)(plo + 128) = vlo1;
        *(float4*)(phi)       = vhi0;
        *(float4*)(phi + 128) = vhi1;
    }
}

// ---------------- launch ----------------
extern "C" void kernel_launch(void* const* d_in, const int* in_sizes, int n_in,
                              void* d_out, int out_size) {
    (void)in_sizes; (void)n_in; (void)out_size;
    const float* x  = (const float*)d_in[0];
    const float* s0 = (const float*)d_in[1];
    const float* s1 = (const float*)d_in[2];
    const float* s2 = (const float*)d_in[3];
    const float* Wm = (const float*)d_in[4];
    const float* bb = (const float*)d_in[5];
    float* out = (float*)d_out;

    // 1) x -> Xt[(c,n,l)]  and  H rows 0..31 (concat block 0)
    transpose_kernel<<<dim3(VN, NC / 128), 128>>>(x);
    // 1b) S2_s = A_s * A_s
    square_support<<<dim3(VN / 64, VN / 64, 3), 256>>>(s0, s1, s2);
    // 2) all 6 propagations in ONE launch; coalesced writes into H blocks 1..6
    prop_gemm<<<dim3(MCOLS / BNT, VN / BM, 6), 256>>>(s0, s1, s2);
    // 3) epilogue GEMM: out = W * H + b
    mix_gemm<<<dim3(NM / 256), 256>>>(Wm, bb, out);
}

// round 10
// speedup vs baseline: 1.6135x; 1.6135x over previous
#include <cuda_runtime.h>
#include <cstdint>

// ---------------- problem constants ----------------
#define VN     512          // graph nodes
#define LN     13           // sequence length
#define BB     64           // batch
#define CN     32           // in channels
#define NC     (BB*CN)      // 2048
#define MCOLS  (NC*LN)      // 26624 (= 208*128)
#define CO     64           // out channels
#define CCAT   224          // 7*CN
#define KDIM   VN
#define VLN    6656         // V*L

// propagation tiling (R7 proven config)
#define BM  128
#define BNT 128
#define BK  16

// mix tiling
#define MV  16              // v per block
#define CK  8               // c chunk (k-step group)
#define NCHUNK 28           // 7 j * 4 c-chunks

// scratch
__device__ float g_Xt[(size_t)VN * MCOLS];            // Xt[v][(n,c,l)]  col = n*416+c*13+l
__device__ float g_Y [6][(size_t)VN * MCOLS];         // Y[yi][w][(n,c,l)], yi: 0=Y1_0,1=Y2_0,2=Y1_1,...
__device__ float g_S2[3 * (size_t)VN * VN];           // squared supports

// ---------------- packed f32x2 helpers ----------------
__device__ __forceinline__ unsigned long long pack_dup(float b) {
    unsigned long long r;
    asm("mov.b64 %0, {%1, %1};" : "=l"(r) : "f"(b));
    return r;
}
__device__ __forceinline__ void fma2(unsigned long long &d,
                                     unsigned long long a,
                                     unsigned long long b) {
    asm("fma.rn.f32x2 %0, %1, %2, %0;" : "+l"(d) : "l"(a), "l"(b));
}
__device__ __forceinline__ float lo32(unsigned long long v) {
    return __uint_as_float((unsigned)(v & 0xffffffffull));
}
__device__ __forceinline__ float hi32(unsigned long long v) {
    return __uint_as_float((unsigned)(v >> 32));
}
__device__ __forceinline__ unsigned s2u(const void* p) {
    return (unsigned)__cvta_generic_to_shared(p);
}
__device__ __forceinline__ void cpa4(unsigned dst, const float* src) {
    asm volatile("cp.async.ca.shared.global [%0], [%1], 4;" :: "r"(dst), "l"(src));
}

// ---------------- 1) transpose x[n,c,v,l] -> Xt[v][(n,c,l)] -----------------
__global__ void transpose_kernel(const float* __restrict__ x) {
    int v  = blockIdx.x;
    int nc = blockIdx.y * blockDim.x + threadIdx.x;
    const float* src = x + (size_t)nc * (VN * LN) + v * LN;
    float* dst = g_Xt + (size_t)v * MCOLS + nc * LN;
#pragma unroll
    for (int l = 0; l < LN; ++l) dst[l] = src[l];
}

// ---------------- 1b) square supports: S2 = A * A ---------------------------
__global__ void __launch_bounds__(256) square_support(
    const float* __restrict__ A0, const float* __restrict__ A1,
    const float* __restrict__ A2)
{
    const int z = blockIdx.z;
    const float* __restrict__ A = (z == 0) ? A0 : ((z == 1) ? A1 : A2);
    float* __restrict__ C = g_S2 + (size_t)z * VN * VN;

    const int i0 = blockIdx.y * 64;
    const int j0 = blockIdx.x * 64;

    __shared__ __align__(16) float As[64][16];
    __shared__ __align__(16) float Bs[16][64];

    const int tid = threadIdx.x;
    const int ty = tid >> 4, tx = tid & 15;
    const int ar = tid >> 2, ac = (tid & 3) * 4;
    const int br = tid >> 4, bc = (tid & 15) * 4;

    float acc[4][4];
#pragma unroll
    for (int i = 0; i < 4; ++i)
#pragma unroll
        for (int j = 0; j < 4; ++j) acc[i][j] = 0.f;

    for (int k0 = 0; k0 < VN; k0 += 16) {
        float4 av = *(const float4*)(A + (size_t)(i0 + ar) * VN + k0 + ac);
        float4 bv = *(const float4*)(A + (size_t)(k0 + br) * VN + j0 + bc);
        __syncthreads();
        *(float4*)&As[ar][ac] = av;
        *(float4*)&Bs[br][bc] = bv;
        __syncthreads();
#pragma unroll
        for (int k = 0; k < 16; ++k) {
            float a0 = As[ty*4+0][k], a1 = As[ty*4+1][k];
            float a2 = As[ty*4+2][k], a3 = As[ty*4+3][k];
            float4 b = *(const float4*)&Bs[k][tx*4];
            acc[0][0]+=a0*b.x; acc[0][1]+=a0*b.y; acc[0][2]+=a0*b.z; acc[0][3]+=a0*b.w;
            acc[1][0]+=a1*b.x; acc[1][1]+=a1*b.y; acc[1][2]+=a1*b.z; acc[1][3]+=a1*b.w;
            acc[2][0]+=a2*b.x; acc[2][1]+=a2*b.y; acc[2][2]+=a2*b.z; acc[2][3]+=a2*b.w;
            acc[3][0]+=a3*b.x; acc[3][1]+=a3*b.y; acc[3][2]+=a3*b.z; acc[3][3]+=a3*b.w;
        }
    }
#pragma unroll
    for (int i = 0; i < 4; ++i) {
        float4 v = make_float4(acc[i][0], acc[i][1], acc[i][2], acc[i][3]);
        *(float4*)(C + (size_t)(i0 + ty*4 + i) * VN + j0 + tx*4) = v;
    }
}

// ---------------- 2) propagation SGEMM (R7-proven inner loop) ---------------
// C[w,m] = sum_v A[v,w] * Xt[v,m].  z=0..2: support_z -> Y[2z] (order 1)
//                                   z=3..5: S2_{z-3}  -> Y[2(z-3)+1] (order 2)
__global__ void __launch_bounds__(256) prop_gemm(
    const float* __restrict__ A0, const float* __restrict__ A1,
    const float* __restrict__ A2)
{
    const int z = blockIdx.z;
    const float* __restrict__ A =
        (z == 0) ? A0 : (z == 1) ? A1 : (z == 2) ? A2
                  : (g_S2 + (size_t)(z - 3) * VN * VN);
    const int yi = (z < 3) ? (2 * z) : (2 * (z - 3) + 1);
    float* __restrict__ Cm = g_Y[yi];
    const float* __restrict__ Bm = g_Xt;

    const int w0 = blockIdx.y * BM;
    const int m0 = blockIdx.x * BNT;

    __shared__ __align__(16) float As[2][BK][BM];
    __shared__ __align__(16) float Bs[2][BK][BNT];

    const int tid = threadIdx.x;
    const int lk = tid >> 5;
    const int lq = tid & 31;
    const int ty = tid >> 4;
    const int tx = tid & 15;

    const float* Ag = A  + (size_t)lk * VN    + w0 + lq * 4;
    const float* Bg = Bm + (size_t)lk * MCOLS + m0 + lq * 4;

    unsigned long long acc[4][8];
#pragma unroll
    for (int i = 0; i < 4; ++i)
#pragma unroll
        for (int j = 0; j < 8; ++j) acc[i][j] = 0ull;

    {
        float4 a0 = *(const float4*)Ag;
        float4 a1 = *(const float4*)(Ag + 8 * VN);
        float4 b0 = *(const float4*)Bg;
        float4 b1 = *(const float4*)(Bg + 8 * MCOLS);
        *(float4*)&As[0][lk    ][lq * 4] = a0;
        *(float4*)&As[0][lk + 8][lq * 4] = a1;
        *(float4*)&Bs[0][lk    ][lq * 4] = b0;
        *(float4*)&Bs[0][lk + 8][lq * 4] = b1;
    }
    __syncthreads();

    int buf = 0;
#pragma unroll 1
    for (int kt = 0; kt < KDIM / BK; ++kt) {
        float4 na0, na1, nb0, nb1;
        const bool has_next = (kt < KDIM / BK - 1);
        if (has_next) {
            const float* Ap = Ag + (size_t)(kt + 1) * (BK * VN);
            const float* Bp = Bg + (size_t)(kt + 1) * (BK * MCOLS);
            na0 = *(const float4*)Ap;
            na1 = *(const float4*)(Ap + 8 * VN);
            nb0 = *(const float4*)Bp;
            nb1 = *(const float4*)(Bp + 8 * MCOLS);
        }
#pragma unroll
        for (int kk = 0; kk < BK; ++kk) {
            ulonglong2 alo = *(const ulonglong2*)&As[buf][kk][ty * 4];
            ulonglong2 ahi = *(const ulonglong2*)&As[buf][kk][64 + ty * 4];
            float4 blo = *(const float4*)&Bs[buf][kk][tx * 4];
            float4 bhi = *(const float4*)&Bs[buf][kk][64 + tx * 4];
            unsigned long long av[4] = {alo.x, alo.y, ahi.x, ahi.y};
            unsigned long long bb[8];
            bb[0] = pack_dup(blo.x); bb[1] = pack_dup(blo.y);
            bb[2] = pack_dup(blo.z); bb[3] = pack_dup(blo.w);
            bb[4] = pack_dup(bhi.x); bb[5] = pack_dup(bhi.y);
            bb[6] = pack_dup(bhi.z); bb[7] = pack_dup(bhi.w);
#pragma unroll
            for (int i = 0; i < 4; ++i)
#pragma unroll
                for (int j = 0; j < 8; ++j)
                    fma2(acc[i][j], av[i], bb[j]);
        }
        if (has_next) {
            int nb = buf ^ 1;
            *(float4*)&As[nb][lk    ][lq * 4] = na0;
            *(float4*)&As[nb][lk + 8][lq * 4] = na1;
            *(float4*)&Bs[nb][lk    ][lq * 4] = nb0;
            *(float4*)&Bs[nb][lk + 8][lq * 4] = nb1;
        }
        __syncthreads();
        buf ^= 1;
    }

#pragma unroll
    for (int ia = 0; ia < 4; ++ia) {
        int rbase = w0 + ((ia >= 2) ? 64 : 0) + ty * 4 + (ia & 1) * 2;
        float* rowlo = Cm + (size_t)rbase * MCOLS;
        float* rowhi = rowlo + MCOLS;
        float4 vlo0 = make_float4(lo32(acc[ia][0]), lo32(acc[ia][1]),
                                  lo32(acc[ia][2]), lo32(acc[ia][3]));
        float4 vlo1 = make_float4(lo32(acc[ia][4]), lo32(acc[ia][5]),
                                  lo32(acc[ia][6]), lo32(acc[ia][7]));
        float4 vhi0 = make_float4(hi32(acc[ia][0]), hi32(acc[ia][1]),
                                  hi32(acc[ia][2]), hi32(acc[ia][3]));
        float4 vhi1 = make_float4(hi32(acc[ia][4]), hi32(acc[ia][5]),
                                  hi32(acc[ia][6]), hi32(acc[ia][7]));
        *(float4*)(rowlo + m0 + tx * 4)      = vlo0;
        *(float4*)(rowlo + m0 + 64 + tx * 4) = vlo1;
        *(float4*)(rowhi + m0 + tx * 4)      = vhi0;
        *(float4*)(rowhi + m0 + 64 + tx * 4) = vhi1;
    }
}

// ---------------- 3) mix GEMM reading Y directly -----------------------------
// Block: one n, 16 v, all 64 o, all 13 l (m = v_l*13+l, 208 cols).
// K = 224 walked in 28 chunks of 8 (j = chunk/4, c0 = (chunk%4)*8).
// B-source: j=0 -> x[n,c,v,l]; j>=1 -> Y[j-1][v][n*416+c*13+l].
__global__ void __launch_bounds__(128) mix_gemm(
    const float* __restrict__ x, const float* __restrict__ Wm,
    const float* __restrict__ bias, float* __restrict__ out)
{
    const int n  = blockIdx.y;
    const int v0 = blockIdx.x * MV;

    __shared__ __align__(16) float Ws[2][CK][CO];          // 4 KB
    __shared__ __align__(16) char  ubuf[32 * 212 * 4];     // 27.1 KB: Bs / Cout
    float (*Bs)[CK][MV][20] = (float (*)[CK][MV][20])ubuf; // [2][8][16][20] = 20.5 KB
    float (*Cout)[212]      = (float (*)[212])ubuf;        // [32][212]

    const int tid = threadIdx.x;
    const int ty = tid >> 4;    // 0..7 -> 8 o
    const int tx = tid & 15;    // 0..15 -> v_l

    unsigned long long acc[4][13];
#pragma unroll
    for (int p = 0; p < 4; ++p)
#pragma unroll
        for (int q = 0; q < 13; ++q) acc[p][q] = 0ull;

    // ---- async prefetch of one chunk ----
    auto prefetch = [&](int jc, int pbuf) {
        int j  = jc >> 2;
        int c0 = (jc & 3) * CK;
        // B tile
        if (j == 0) {
            int v_l = tid & 15, cc = tid >> 4;   // lanes contiguous over v
            const float* src = x + (((size_t)n * CN + c0 + cc) * VN + v0 + v_l) * LN;
            unsigned dst = s2u(&Bs[pbuf][cc][v_l][0]);
#pragma unroll
            for (int q = 0; q < LN; ++q) cpa4(dst + q * 4, src + q);
        } else {
            int v_l = tid >> 3, cc = tid & 7;    // lanes contiguous over c (runs)
            const float* src = g_Y[j - 1] + (size_t)(v0 + v_l) * MCOLS
                             + n * 416 + (c0 + cc) * LN;
            unsigned dst = s2u(&Bs[pbuf][cc][v_l][0]);
#pragma unroll
            for (int q = 0; q < LN; ++q) cpa4(dst + q * 4, src + q);
        }
        // W tile: Ws[kk][o]
#pragma unroll
        for (int i = 0; i < 4; ++i) {
            int p = tid + i * 128;
            int kk = p >> 6, o = p & 63;
            cpa4(s2u(&Ws[pbuf][kk][o]), Wm + o * CCAT + j * CN + c0 + kk);
        }
        asm volatile("cp.async.commit_group;" ::: "memory");
    };

    prefetch(0, 0);
    int buf = 0;
#pragma unroll 1
    for (int jc = 0; jc < NCHUNK; ++jc) {
        if (jc + 1 < NCHUNK) {
            prefetch(jc + 1, buf ^ 1);
            asm volatile("cp.async.wait_group 1;" ::: "memory");
        } else {
            asm volatile("cp.async.wait_group 0;" ::: "memory");
        }
        __syncthreads();
#pragma unroll
        for (int kk = 0; kk < CK; ++kk) {
            ulonglong2 a01 = *(const ulonglong2*)&Ws[buf][kk][ty * 8];
            ulonglong2 a23 = *(const ulonglong2*)&Ws[buf][kk][ty * 8 + 4];
            float4 b0 = *(const float4*)&Bs[buf][kk][tx][0];
            float4 b1 = *(const float4*)&Bs[buf][kk][tx][4];
            float4 b2 = *(const float4*)&Bs[buf][kk][tx][8];
            float4 b3 = *(const float4*)&Bs[buf][kk][tx][12];
            float bv[13] = {b0.x, b0.y, b0.z, b0.w, b1.x, b1.y, b1.z, b1.w,
                            b2.x, b2.y, b2.z, b2.w, b3.x};
            unsigned long long av[4] = {a01.x, a01.y, a23.x, a23.y};
#pragma unroll
            for (int q = 0; q < 13; ++q) {
                unsigned long long bd = pack_dup(bv[q]);
                fma2(acc[0][q], av[0], bd);
                fma2(acc[1][q], av[1], bd);
                fma2(acc[2][q], av[2], bd);
                fma2(acc[3][q], av[3], bd);
            }
        }
        __syncthreads();
        buf ^= 1;
    }

    // ---- epilogue: stage 32-o halves in smem, write coalesced float4 ----
    float bo[8];
#pragma unroll
    for (int p = 0; p < 8; ++p) bo[p] = bias[ty * 8 + p];

#pragma unroll 1
    for (int h2 = 0; h2 < 2; ++h2) {
        if ((ty >> 2) == h2) {
            int orow0 = (ty & 3) * 8;
#pragma unroll
            for (int p = 0; p < 4; ++p)
#pragma unroll
                for (int q = 0; q < 13; ++q) {
                    Cout[orow0 + 2 * p    ][tx * 13 + q] = lo32(acc[p][q]) + bo[2 * p];
                    Cout[orow0 + 2 * p + 1][tx * 13 + q] = hi32(acc[p][q]) + bo[2 * p + 1];
                }
        }
        __syncthreads();
#pragma unroll
        for (int i = 0; i < 13; ++i) {
            int f = tid + i * 128;            // 0..1663
            int row = f / 52, c4 = f - row * 52;
            float4 val = *(const float4*)&Cout[row][c4 * 4];
            *(float4*)(out + ((size_t)n * CO + h2 * 32 + row) * VLN
                           + v0 * LN + c4 * 4) = val;
        }
        __syncthreads();
    }
}

// ---------------- launch ----------------
extern "C" void kernel_launch(void* const* d_in, const int* in_sizes, int n_in,
                              void* d_out, int out_size) {
    (void)in_sizes; (void)n_in; (void)out_size;
    const float* x  = (const float*)d_in[0];
    const float* s0 = (const float*)d_in[1];
    const float* s1 = (const float*)d_in[2];
    const float* s2 = (const float*)d_in[3];
    const float* Wm = (const float*)d_in[4];
    const float* bb = (const float*)d_in[5];
    float* out = (float*)d_out;

    // 1) x -> Xt[(n,c,l)]
    transpose_kernel<<<dim3(VN, NC / 128), 128>>>(x);
    // 1b) S2_s = A_s * A_s
    square_support<<<dim3(VN / 64, VN / 64, 3), 256>>>(s0, s1, s2);
    // 2) all 6 propagations in ONE launch -> Y buffers (natural layout)
    prop_gemm<<<dim3(MCOLS / BNT, VN / BM, 6), 256>>>(s0, s1, s2);
    // 3) mix GEMM reading x + Y directly; fused bias; coalesced output
    mix_gemm<<<dim3(VN / MV, BB), 128>>>(x, Wm, bb, out);
}

// round 11
// speedup vs baseline: 1.7916x; 1.1104x over previous
#include <cuda_runtime.h>
#include <cstdint>

// ---------------- problem constants ----------------
#define VN     512          // graph nodes
#define LN     13           // sequence length
#define BB     64           // batch
#define CN     32           // in channels
#define NC     (BB*CN)      // 2048
#define MCOLS  (NC*LN)      // 26624 (= 208*128)
#define CO     64           // out channels
#define CCAT   224          // 7*CN
#define KDIM   VN
#define VLN    6656         // V*L (= 26*256)

// propagation tiling (proven config)
#define BM  128
#define BNT 128
#define BK  16

// mix tiling
#define EBK 8               // k chunk (8 c of one j)
#define NCHUNK 28           // 7 j * 4 c-chunks

// scratch
__device__ float g_Xt[(size_t)VN * MCOLS];            // Xt[v][(n,c,l)] col = n*416+c*13+l
__device__ float g_Y [6][(size_t)VN * MCOLS];         // Y[yi][w][(n,c,l)]
__device__ float g_S2[3 * (size_t)VN * VN];           // squared supports

// ---------------- packed f32x2 helpers ----------------
__device__ __forceinline__ unsigned long long pack_dup(float b) {
    unsigned long long r;
    asm("mov.b64 %0, {%1, %1};" : "=l"(r) : "f"(b));
    return r;
}
__device__ __forceinline__ void fma2(unsigned long long &d,
                                     unsigned long long a,
                                     unsigned long long b) {
    asm("fma.rn.f32x2 %0, %1, %2, %0;" : "+l"(d) : "l"(a), "l"(b));
}
__device__ __forceinline__ float lo32(unsigned long long v) {
    return __uint_as_float((unsigned)(v & 0xffffffffull));
}
__device__ __forceinline__ float hi32(unsigned long long v) {
    return __uint_as_float((unsigned)(v >> 32));
}

// ---------------- 1) transpose x[n,c,v,l] -> Xt[v][(n,c,l)] -----------------
__global__ void transpose_kernel(const float* __restrict__ x) {
    int v  = blockIdx.x;
    int nc = blockIdx.y * blockDim.x + threadIdx.x;
    const float* src = x + (size_t)nc * (VN * LN) + v * LN;
    float* dst = g_Xt + (size_t)v * MCOLS + nc * LN;
#pragma unroll
    for (int l = 0; l < LN; ++l) dst[l] = src[l];
}

// ---------------- 1b) square supports: S2 = A * A ---------------------------
__global__ void __launch_bounds__(256) square_support(
    const float* __restrict__ A0, const float* __restrict__ A1,
    const float* __restrict__ A2)
{
    const int z = blockIdx.z;
    const float* __restrict__ A = (z == 0) ? A0 : ((z == 1) ? A1 : A2);
    float* __restrict__ C = g_S2 + (size_t)z * VN * VN;

    const int i0 = blockIdx.y * 64;
    const int j0 = blockIdx.x * 64;

    __shared__ __align__(16) float As[64][16];
    __shared__ __align__(16) float Bs[16][64];

    const int tid = threadIdx.x;
    const int ty = tid >> 4, tx = tid & 15;
    const int ar = tid >> 2, ac = (tid & 3) * 4;
    const int br = tid >> 4, bc = (tid & 15) * 4;

    float acc[4][4];
#pragma unroll
    for (int i = 0; i < 4; ++i)
#pragma unroll
        for (int j = 0; j < 4; ++j) acc[i][j] = 0.f;

    for (int k0 = 0; k0 < VN; k0 += 16) {
        float4 av = *(const float4*)(A + (size_t)(i0 + ar) * VN + k0 + ac);
        float4 bv = *(const float4*)(A + (size_t)(k0 + br) * VN + j0 + bc);
        __syncthreads();
        *(float4*)&As[ar][ac] = av;
        *(float4*)&Bs[br][bc] = bv;
        __syncthreads();
#pragma unroll
        for (int k = 0; k < 16; ++k) {
            float a0 = As[ty*4+0][k], a1 = As[ty*4+1][k];
            float a2 = As[ty*4+2][k], a3 = As[ty*4+3][k];
            float4 b = *(const float4*)&Bs[k][tx*4];
            acc[0][0]+=a0*b.x; acc[0][1]+=a0*b.y; acc[0][2]+=a0*b.z; acc[0][3]+=a0*b.w;
            acc[1][0]+=a1*b.x; acc[1][1]+=a1*b.y; acc[1][2]+=a1*b.z; acc[1][3]+=a1*b.w;
            acc[2][0]+=a2*b.x; acc[2][1]+=a2*b.y; acc[2][2]+=a2*b.z; acc[2][3]+=a2*b.w;
            acc[3][0]+=a3*b.x; acc[3][1]+=a3*b.y; acc[3][2]+=a3*b.z; acc[3][3]+=a3*b.w;
        }
    }
#pragma unroll
    for (int i = 0; i < 4; ++i) {
        float4 v = make_float4(acc[i][0], acc[i][1], acc[i][2], acc[i][3]);
        *(float4*)(C + (size_t)(i0 + ty*4 + i) * VN + j0 + tx*4) = v;
    }
}

// ---------------- 2) propagation SGEMM (proven inner loop) ------------------
__global__ void __launch_bounds__(256) prop_gemm(
    const float* __restrict__ A0, const float* __restrict__ A1,
    const float* __restrict__ A2)
{
    const int z = blockIdx.z;
    const float* __restrict__ A =
        (z == 0) ? A0 : (z == 1) ? A1 : (z == 2) ? A2
                  : (g_S2 + (size_t)(z - 3) * VN * VN);
    const int yi = (z < 3) ? (2 * z) : (2 * (z - 3) + 1);
    float* __restrict__ Cm = g_Y[yi];
    const float* __restrict__ Bm = g_Xt;

    const int w0 = blockIdx.y * BM;
    const int m0 = blockIdx.x * BNT;

    __shared__ __align__(16) float As[2][BK][BM];
    __shared__ __align__(16) float Bs[2][BK][BNT];

    const int tid = threadIdx.x;
    const int lk = tid >> 5;
    const int lq = tid & 31;
    const int ty = tid >> 4;
    const int tx = tid & 15;

    const float* Ag = A  + (size_t)lk * VN    + w0 + lq * 4;
    const float* Bg = Bm + (size_t)lk * MCOLS + m0 + lq * 4;

    unsigned long long acc[4][8];
#pragma unroll
    for (int i = 0; i < 4; ++i)
#pragma unroll
        for (int j = 0; j < 8; ++j) acc[i][j] = 0ull;

    {
        float4 a0 = *(const float4*)Ag;
        float4 a1 = *(const float4*)(Ag + 8 * VN);
        float4 b0 = *(const float4*)Bg;
        float4 b1 = *(const float4*)(Bg + 8 * MCOLS);
        *(float4*)&As[0][lk    ][lq * 4] = a0;
        *(float4*)&As[0][lk + 8][lq * 4] = a1;
        *(float4*)&Bs[0][lk    ][lq * 4] = b0;
        *(float4*)&Bs[0][lk + 8][lq * 4] = b1;
    }
    __syncthreads();

    int buf = 0;
#pragma unroll 1
    for (int kt = 0; kt < KDIM / BK; ++kt) {
        float4 na0, na1, nb0, nb1;
        const bool has_next = (kt < KDIM / BK - 1);
        if (has_next) {
            const float* Ap = Ag + (size_t)(kt + 1) * (BK * VN);
            const float* Bp = Bg + (size_t)(kt + 1) * (BK * MCOLS);
            na0 = *(const float4*)Ap;
            na1 = *(const float4*)(Ap + 8 * VN);
            nb0 = *(const float4*)Bp;
            nb1 = *(const float4*)(Bp + 8 * MCOLS);
        }
#pragma unroll
        for (int kk = 0; kk < BK; ++kk) {
            ulonglong2 alo = *(const ulonglong2*)&As[buf][kk][ty * 4];
            ulonglong2 ahi = *(const ulonglong2*)&As[buf][kk][64 + ty * 4];
            float4 blo = *(const float4*)&Bs[buf][kk][tx * 4];
            float4 bhi = *(const float4*)&Bs[buf][kk][64 + tx * 4];
            unsigned long long av[4] = {alo.x, alo.y, ahi.x, ahi.y};
            unsigned long long bb[8];
            bb[0] = pack_dup(blo.x); bb[1] = pack_dup(blo.y);
            bb[2] = pack_dup(blo.z); bb[3] = pack_dup(blo.w);
            bb[4] = pack_dup(bhi.x); bb[5] = pack_dup(bhi.y);
            bb[6] = pack_dup(bhi.z); bb[7] = pack_dup(bhi.w);
#pragma unroll
            for (int i = 0; i < 4; ++i)
#pragma unroll
                for (int j = 0; j < 8; ++j)
                    fma2(acc[i][j], av[i], bb[j]);
        }
        if (has_next) {
            int nb = buf ^ 1;
            *(float4*)&As[nb][lk    ][lq * 4] = na0;
            *(float4*)&As[nb][lk + 8][lq * 4] = na1;
            *(float4*)&Bs[nb][lk    ][lq * 4] = nb0;
            *(float4*)&Bs[nb][lk + 8][lq * 4] = nb1;
        }
        __syncthreads();
        buf ^= 1;
    }

#pragma unroll
    for (int ia = 0; ia < 4; ++ia) {
        int rbase = w0 + ((ia >= 2) ? 64 : 0) + ty * 4 + (ia & 1) * 2;
        float* rowlo = Cm + (size_t)rbase * MCOLS;
        float* rowhi = rowlo + MCOLS;
        float4 vlo0 = make_float4(lo32(acc[ia][0]), lo32(acc[ia][1]),
                                  lo32(acc[ia][2]), lo32(acc[ia][3]));
        float4 vlo1 = make_float4(lo32(acc[ia][4]), lo32(acc[ia][5]),
                                  lo32(acc[ia][6]), lo32(acc[ia][7]));
        float4 vhi0 = make_float4(hi32(acc[ia][0]), hi32(acc[ia][1]),
                                  hi32(acc[ia][2]), hi32(acc[ia][3]));
        float4 vhi1 = make_float4(hi32(acc[ia][4]), hi32(acc[ia][5]),
                                  hi32(acc[ia][6]), hi32(acc[ia][7]));
        *(float4*)(rowlo + m0 + tx * 4)      = vlo0;
        *(float4*)(rowlo + m0 + 64 + tx * 4) = vlo1;
        *(float4*)(rowhi + m0 + tx * 4)      = vhi0;
        *(float4*)(rowhi + m0 + 64 + tx * 4) = vhi1;
    }
}

// ---------------- 3) mix GEMM: out = W*[x;Y] + b, R8 inner loop -------------
// Block: one n, m-tile = 256 consecutive (v,l) (26 tiles per n, 1664 blocks).
// K = 224 in 28 chunks (j = jc>>2, c0 = (jc&3)*8).
// B staging: j=0 from x (m-contiguous); j>=1 from Y rows: per v one
// contiguous 104-float run (8c x 13l), scattered into Bs[c][m] in smem.
__global__ void __launch_bounds__(256, 2) mix_gemm(
    const float* __restrict__ x, const float* __restrict__ Wm,
    const float* __restrict__ bias, float* __restrict__ out)
{
    const int bid = blockIdx.x;
    const int n   = bid / 26;
    const int m0  = (bid - n * 26) * 256;   // within n's 6656 (v,l) block

    __shared__ __align__(16) float Ws[2][EBK][CO];     // 4 KB
    __shared__ __align__(16) float Bs[2][EBK][256];    // 16 KB

    const int tid = threadIdx.x;
    const int ty  = tid >> 5;    // 0..7  (o quad row)
    const int tx  = tid & 31;    // 0..31 (m quad col)
    const int wo_ = tid & 63;    // W load: o
    const int wk_ = tid >> 6;    // W load: kk (0..3; +4)

    const int v_lo = m0 / 13;
    const int r0   = m0 - v_lo * 13;        // 0..12

    unsigned long long acc[4][8];
#pragma unroll
    for (int i = 0; i < 4; ++i)
#pragma unroll
        for (int jj = 0; jj < 8; ++jj) acc[i][jj] = 0ull;

    float4 pb[3];
    float  pw0, pw1;

    // ---- prefetch chunk jc into registers ----
    auto prefetch = [&](int jc) {
        const int j  = jc >> 2;
        const int c0 = (jc & 3) * EBK;
        if (j == 0) {
            const float* base = x + ((size_t)(n * CN + c0)) * VLN + m0;
#pragma unroll
            for (int t = 0; t < 2; ++t) {
                int e  = tid + t * 256;          // 0..511
                int cr = e >> 6, f4 = e & 63;
                pb[t] = *(const float4*)(base + (size_t)cr * VLN + f4 * 4);
            }
        } else {
            const float* base = g_Y[j - 1] + n * 416 + c0 * LN;
#pragma unroll
            for (int t = 0; t < 3; ++t) {
                int e = tid + t * 256;           // task: (v_rel, f4)
                if (e < 546) {
                    int vr = e / 26, f4 = e - vr * 26;
                    if (v_lo + vr < VN)
                        pb[t] = *(const float4*)(base + (size_t)(v_lo + vr) * MCOLS
                                                      + f4 * 4);
                }
            }
        }
        pw0 = Wm[wo_ * CCAT + j * CN + c0 + wk_];
        pw1 = Wm[wo_ * CCAT + j * CN + c0 + wk_ + 4];
    };

    // ---- store prefetched chunk into buffer pbuf ----
    auto stage = [&](int jc, int pbuf) {
        const int j = jc >> 2;
        if (j == 0) {
#pragma unroll
            for (int t = 0; t < 2; ++t) {
                int e  = tid + t * 256;
                int cr = e >> 6, f4 = e & 63;
                *(float4*)&Bs[pbuf][cr][f4 * 4] = pb[t];
            }
        } else {
#pragma unroll
            for (int t = 0; t < 3; ++t) {
                int e = tid + t * 256;
                if (e < 546) {
                    int vr = e / 26, f4 = e - vr * 26;
                    if (v_lo + vr < VN) {
                        int cb = vr * 13 - r0;      // col = cb + l
                        float vals[4] = {pb[t].x, pb[t].y, pb[t].z, pb[t].w};
#pragma unroll
                        for (int i = 0; i < 4; ++i) {
                            int elem = f4 * 4 + i;       // 0..103
                            int cr = elem / 13;
                            int l  = elem - cr * 13;
                            int col = cb + l;
                            if (col >= 0 && col < 256)
                                Bs[pbuf][cr][col] = vals[i];
                        }
                    }
                }
            }
        }
        Ws[pbuf][wk_][wo_]     = pw0;
        Ws[pbuf][wk_ + 4][wo_] = pw1;
    };

    prefetch(0);
    stage(0, 0);
    __syncthreads();

    int buf = 0;
#pragma unroll 1
    for (int jc = 0; jc < NCHUNK; ++jc) {
        const bool has_next = (jc + 1 < NCHUNK);
        if (has_next) prefetch(jc + 1);
#pragma unroll
        for (int kk = 0; kk < EBK; ++kk) {
            ulonglong2 a01 = *(const ulonglong2*)&Ws[buf][kk][ty * 4];
            ulonglong2 a23 = *(const ulonglong2*)&Ws[buf][kk][32 + ty * 4];
            float4 blo = *(const float4*)&Bs[buf][kk][tx * 4];
            float4 bhi = *(const float4*)&Bs[buf][kk][128 + tx * 4];
            unsigned long long av[4] = {a01.x, a01.y, a23.x, a23.y};
            unsigned long long bb[8];
            bb[0] = pack_dup(blo.x); bb[1] = pack_dup(blo.y);
            bb[2] = pack_dup(blo.z); bb[3] = pack_dup(blo.w);
            bb[4] = pack_dup(bhi.x); bb[5] = pack_dup(bhi.y);
            bb[6] = pack_dup(bhi.z); bb[7] = pack_dup(bhi.w);
#pragma unroll
            for (int i = 0; i < 4; ++i)
#pragma unroll
                for (int jj = 0; jj < 8; ++jj)
                    fma2(acc[i][jj], av[i], bb[jj]);
        }
        if (has_next) stage(jc + 1, buf ^ 1);
        __syncthreads();
        buf ^= 1;
    }

    // ---- write out: tile lies entirely within one n ----
#pragma unroll
    for (int ia = 0; ia < 4; ++ia) {
        int o0 = ((ia >= 2) ? 32 : 0) + ty * 4 + (ia & 1) * 2;
        float blo = bias[o0], bhi = bias[o0 + 1];
        float* plo = out + ((size_t)n * CO + o0) * VLN + m0 + tx * 4;
        float* phi = plo + VLN;
        float4 vlo0 = make_float4(lo32(acc[ia][0]) + blo, lo32(acc[ia][1]) + blo,
                                  lo32(acc[ia][2]) + blo, lo32(acc[ia][3]) + blo);
        float4 vlo1 = make_float4(lo32(acc[ia][4]) + blo, lo32(acc[ia][5]) + blo,
                                  lo32(acc[ia][6]) + blo, lo32(acc[ia][7]) + blo);
        float4 vhi0 = make_float4(hi32(acc[ia][0]) + bhi, hi32(acc[ia][1]) + bhi,
                                  hi32(acc[ia][2]) + bhi, hi32(acc[ia][3]) + bhi);
        float4 vhi1 = make_float4(hi32(acc[ia][4]) + bhi, hi32(acc[ia][5]) + bhi,
                                  hi32(acc[ia][6]) + bhi, hi32(acc[ia][7]) + bhi);
        *(float4*)(plo)       = vlo0;
        *(float4*)(plo + 128) = vlo1;
        *(float4*)(phi)       = vhi0;
        *(float4*)(phi + 128) = vhi1;
    }
}

// ---------------- launch ----------------
extern "C" void kernel_launch(void* const* d_in, const int* in_sizes, int n_in,
                              void* d_out, int out_size) {
    (void)in_sizes; (void)n_in; (void)out_size;
    const float* x  = (const float*)d_in[0];
    const float* s0 = (const float*)d_in[1];
    const float* s1 = (const float*)d_in[2];
    const float* s2 = (const float*)d_in[3];
    const float* Wm = (const float*)d_in[4];
    const float* bb = (const float*)d_in[5];
    float* out = (float*)d_out;

    // 1) x -> Xt[(n,c,l)]
    transpose_kernel<<<dim3(VN, NC / 128), 128>>>(x);
    // 1b) S2_s = A_s * A_s  (parallelizes order-2 propagation)
    square_support<<<dim3(VN / 64, VN / 64, 3), 256>>>(s0, s1, s2);
    // 2) all 6 propagations in ONE launch -> Y (natural layout, float4 stores)
    prop_gemm<<<dim3(MCOLS / BNT, VN / BM, 6), 256>>>(s0, s1, s2);
    // 3) mix GEMM: R8-shaped inner loop, B staged from x/Y with smem transpose
    mix_gemm<<<dim3(BB * 26), 256>>>(x, Wm, bb, out);
}

// round 16
// speedup vs baseline: 2.1789x; 1.2162x over previous
#include <cuda_runtime.h>
#include <cuda_bf16.h>
#include <cstdint>

// ---------------- problem constants ----------------
#define VN     512          // graph nodes
#define LN     13           // sequence length
#define BB     64           // batch
#define CN     32           // in channels
#define NC     (BB*CN)      // 2048
#define MCOLS  (NC*LN)      // 26624
#define CO     64           // out channels
#define CCAT   224          // 7*CN
#define VLN    6656         // V*L

// mix tiling
#define EBK 8
#define NCHUNK 28

// ---------------- scratch (device globals; no allocs) ----------------
__device__ __align__(1024) __nv_bfloat16 g_XtT_hi[(size_t)MCOLS * VN];  // [m][v]
__device__ __align__(1024) __nv_bfloat16 g_XtT_lo[(size_t)MCOLS * VN];
__device__ __align__(1024) __nv_bfloat16 g_AT_hi[6][(size_t)VN * VN];   // [w][v]
__device__ __align__(1024) __nv_bfloat16 g_AT_lo[6][(size_t)VN * VN];
__device__ __align__(1024) float g_S2[3][(size_t)VN * VN];              // A*A fp32
__device__ __align__(1024) float g_Y[6][(size_t)VN * MCOLS];            // [w][(n,c,l)]

// ---------------- packed f32x2 helpers (mix GEMM) ----------------
__device__ __forceinline__ unsigned long long pack_dup(float b) {
    unsigned long long r;
    asm("mov.b64 %0, {%1, %1};" : "=l"(r) : "f"(b));
    return r;
}
__device__ __forceinline__ void fma2(unsigned long long &d,
                                     unsigned long long a,
                                     unsigned long long b) {
    asm("fma.rn.f32x2 %0, %1, %2, %0;" : "+l"(d) : "l"(a), "l"(b));
}
__device__ __forceinline__ float lo32(unsigned long long v) {
    return __uint_as_float((unsigned)(v & 0xffffffffull));
}
__device__ __forceinline__ float hi32(unsigned long long v) {
    return __uint_as_float((unsigned)(v >> 32));
}

// ---------------- smem / mma.sync helpers (sm_80-compatible PTX) ------------
__device__ __forceinline__ uint32_t smem_u32(const void* p) {
    uint32_t a;
    asm("{ .reg .u64 t; cvta.to.shared.u64 t, %1; cvt.u32.u64 %0, t; }"
        : "=r"(a) : "l"(p));
    return a;
}
__device__ __forceinline__ void ldm4(uint32_t* r, uint32_t addr) {
    asm volatile("ldmatrix.sync.aligned.m8n8.x4.shared.b16 {%0,%1,%2,%3}, [%4];"
                 : "=r"(r[0]), "=r"(r[1]), "=r"(r[2]), "=r"(r[3]) : "r"(addr));
}
__device__ __forceinline__ void mma16816(float* c, const uint32_t* a,
                                         const uint32_t* b) {
    asm volatile("mma.sync.aligned.m16n8k16.row.col.f32.bf16.bf16.f32 "
                 "{%0,%1,%2,%3}, {%4,%5,%6,%7}, {%8,%9}, {%0,%1,%2,%3};"
                 : "+f"(c[0]), "+f"(c[1]), "+f"(c[2]), "+f"(c[3])
                 : "r"(a[0]), "r"(a[1]), "r"(a[2]), "r"(a[3]),
                   "r"(b[0]), "r"(b[1]));
}

// ---------------- 1) square supports: S2 = A * A (fp32) ---------------------
__global__ void __launch_bounds__(256) square_support(
    const float* __restrict__ A0, const float* __restrict__ A1,
    const float* __restrict__ A2)
{
    const int z = blockIdx.z;
    const float* __restrict__ A = (z == 0) ? A0 : ((z == 1) ? A1 : A2);
    float* __restrict__ C = g_S2[z];

    const int i0 = blockIdx.y * 64;
    const int j0 = blockIdx.x * 64;

    __shared__ __align__(16) float As[64][16];
    __shared__ __align__(16) float Bs[16][64];

    const int tid = threadIdx.x;
    const int ty = tid >> 4, tx = tid & 15;
    const int ar = tid >> 2, ac = (tid & 3) * 4;
    const int br = tid >> 4, bc = (tid & 15) * 4;

    float acc[4][4];
#pragma unroll
    for (int i = 0; i < 4; ++i)
#pragma unroll
        for (int j = 0; j < 4; ++j) acc[i][j] = 0.f;

    for (int k0 = 0; k0 < VN; k0 += 16) {
        float4 av = *(const float4*)(A + (size_t)(i0 + ar) * VN + k0 + ac);
        float4 bv = *(const float4*)(A + (size_t)(k0 + br) * VN + j0 + bc);
        __syncthreads();
        *(float4*)&As[ar][ac] = av;
        *(float4*)&Bs[br][bc] = bv;
        __syncthreads();
#pragma unroll
        for (int k = 0; k < 16; ++k) {
            float a0 = As[ty*4+0][k], a1 = As[ty*4+1][k];
            float a2 = As[ty*4+2][k], a3 = As[ty*4+3][k];
            float4 b = *(const float4*)&Bs[k][tx*4];
            acc[0][0]+=a0*b.x; acc[0][1]+=a0*b.y; acc[0][2]+=a0*b.z; acc[0][3]+=a0*b.w;
            acc[1][0]+=a1*b.x; acc[1][1]+=a1*b.y; acc[1][2]+=a1*b.z; acc[1][3]+=a1*b.w;
            acc[2][0]+=a2*b.x; acc[2][1]+=a2*b.y; acc[2][2]+=a2*b.z; acc[2][3]+=a2*b.w;
            acc[3][0]+=a3*b.x; acc[3][1]+=a3*b.y; acc[3][2]+=a3*b.z; acc[3][3]+=a3*b.w;
        }
    }
#pragma unroll
    for (int i = 0; i < 4; ++i) {
        float4 v = make_float4(acc[i][0], acc[i][1], acc[i][2], acc[i][3]);
        *(float4*)(C + (size_t)(i0 + ty*4 + i) * VN + j0 + tx*4) = v;
    }
}

// ---------------- 2) transpose + bf16 split of supports / S2 ----------------
__global__ void __launch_bounds__(256) trans_split(
    const float* __restrict__ A0, const float* __restrict__ A1,
    const float* __restrict__ A2)
{
    const int z = blockIdx.z;
    const float* __restrict__ src =
        (z == 0) ? A0 : (z == 1) ? A1 : (z == 2) ? A2 : g_S2[z - 3];
    const int v0 = blockIdx.y * 32;
    const int w0 = blockIdx.x * 32;

    __shared__ float sm[32][33];
    const int ti = threadIdx.x >> 5, tj = threadIdx.x & 31;
#pragma unroll
    for (int r = 0; r < 4; ++r)
        sm[ti + 8*r][tj] = src[(size_t)(v0 + ti + 8*r) * VN + w0 + tj];
    __syncthreads();
#pragma unroll
    for (int r = 0; r < 4; ++r) {
        int w = w0 + ti + 8*r;
        float val = sm[tj][ti + 8*r];
        __nv_bfloat16 hi = __float2bfloat16(val);
        __nv_bfloat16 lo = __float2bfloat16(val - __bfloat162float(hi));
        g_AT_hi[z][(size_t)w * VN + v0 + tj] = hi;
        g_AT_lo[z][(size_t)w * VN + v0 + tj] = lo;
    }
}

// ---------------- 3) x -> XtT[m][v] bf16 hi/lo (m = n*416+c*13+l) -----------
__global__ void __launch_bounds__(256) conv_xtT(const float* __restrict__ x) {
    const int nc = blockIdx.x;
    __shared__ float s[VLN];
    const float4* src = (const float4*)(x + (size_t)nc * VLN);
    for (int i = threadIdx.x; i < VLN / 4; i += 256)
        ((float4*)s)[i] = src[i];
    __syncthreads();
    const int t = threadIdx.x;
#pragma unroll
    for (int l = 0; l < LN; ++l) {
        float f0 = s[(2*t)     * LN + l];
        float f1 = s[(2*t + 1) * LN + l];
        __nv_bfloat16 h0 = __float2bfloat16(f0);
        __nv_bfloat16 h1 = __float2bfloat16(f1);
        __nv_bfloat16 l0 = __float2bfloat16(f0 - __bfloat162float(h0));
        __nv_bfloat16 l1 = __float2bfloat16(f1 - __bfloat162float(h1));
        size_t row = (size_t)(nc * LN + l) * VN;
        *(__nv_bfloat162*)(g_XtT_hi + row + 2*t) = __halves2bfloat162(h0, h1);
        *(__nv_bfloat162*)(g_XtT_lo + row + 2*t) = __halves2bfloat162(l0, l1);
    }
}

// ---------------- 4) propagation via mma.sync (legacy tensor cores) ---------
// Y[w,m] = sum_v AT[w,v] * XtT[m,v]; 3 passes (hh, hl, lh) into fp32 accums.
// CTA: 128w x 128m, K=512 in 32 chunks of 16. 512 threads = 16 warps (4x4),
// warp tile 32x32. Smem rows padded to 48B -> conflict-free ldmatrix.
__global__ void __launch_bounds__(512) mma_prop()
{
    __shared__ __align__(16) char sm[49152];   // 2 bufs x (4 mats x 128 x 48B)

    const int z  = blockIdx.z;
    const int w0 = blockIdx.y * 128;
    const int m0 = blockIdx.x * 128;
    const int yi = (z < 3) ? 2 * z : 2 * (z - 3) + 1;

    const int tid  = threadIdx.x;
    const int lane = tid & 31;
    const int wid  = tid >> 5;
    const int wr = wid >> 2, wc = wid & 3;

    // staging: 1024 16B-tasks, 2 per thread. task e: mat = e>>8 (Ah,Al,Bh,Bl),
    // row = (e&255)>>1, seg = e&1.
    const __nv_bfloat16* gp[2];
    uint32_t sp[2];
#pragma unroll
    for (int t = 0; t < 2; ++t) {
        int e = tid + t * 512;
        int me = e >> 8, row = (e & 255) >> 1, seg = e & 1;
        const __nv_bfloat16* base =
            (me == 0) ? g_AT_hi[z] : (me == 1) ? g_AT_lo[z]
          : (me == 2) ? g_XtT_hi : g_XtT_lo;
        int grow = ((me < 2) ? w0 : m0) + row;
        gp[t] = base + (size_t)grow * VN + seg * 8;
        sp[t] = (uint32_t)(me * 6144 + row * 48 + seg * 16);
    }
    const uint32_t smb = smem_u32(sm);

    // ldmatrix lane address offsets (within one buffer)
    uint32_t a_off[2], b_off[2];
#pragma unroll
    for (int i = 0; i < 2; ++i)
        a_off[i] = (uint32_t)((wr*32 + i*16 + (lane & 15)) * 48 + (lane >> 4) * 16);
#pragma unroll
    for (int p = 0; p < 2; ++p)
        b_off[p] = (uint32_t)((wc*32 + p*16 + (lane & 7) + ((lane >> 4) << 3)) * 48
                              + ((lane >> 3) & 1) * 16);

    float c[2][4][4];
#pragma unroll
    for (int i = 0; i < 2; ++i)
#pragma unroll
        for (int j = 0; j < 4; ++j)
#pragma unroll
            for (int q = 0; q < 4; ++q) c[i][j][q] = 0.f;

    // prologue: chunk 0 -> buf 0
    uint4 pre[2];
#pragma unroll
    for (int t = 0; t < 2; ++t) pre[t] = *(const uint4*)gp[t];
#pragma unroll
    for (int t = 0; t < 2; ++t) *(uint4*)(sm + sp[t]) = pre[t];
    __syncthreads();

    int buf = 0;
#pragma unroll 1
    for (int kc = 0; kc < 32; ++kc) {
        const bool has_next = (kc < 31);
        if (has_next) {
#pragma unroll
            for (int t = 0; t < 2; ++t)
                pre[t] = *(const uint4*)(gp[t] + (size_t)(kc + 1) * 16);
        }
        const uint32_t bb = smb + (uint32_t)buf * 24576;
        uint32_t ah[2][4], al[2][4], bhf[2][4], blf[2][4];
#pragma unroll
        for (int i = 0; i < 2; ++i) {
            ldm4(ah[i], bb + 0    + a_off[i]);
            ldm4(al[i], bb + 6144 + a_off[i]);
        }
#pragma unroll
        for (int p = 0; p < 2; ++p) {
            ldm4(bhf[p], bb + 12288 + b_off[p]);
            ldm4(blf[p], bb + 18432 + b_off[p]);
        }
#pragma unroll
        for (int i = 0; i < 2; ++i)
#pragma unroll
            for (int j = 0; j < 4; ++j) {
                const uint32_t* bH = &bhf[j >> 1][(j & 1) * 2];
                const uint32_t* bL = &blf[j >> 1][(j & 1) * 2];
                mma16816(c[i][j], ah[i], bH);   // hi*hi
                mma16816(c[i][j], ah[i], bL);   // hi*lo
                mma16816(c[i][j], al[i], bH);   // lo*hi
            }
        if (has_next) {
            char* nb = sm + (buf ^ 1) * 24576;
#pragma unroll
            for (int t = 0; t < 2; ++t) *(uint4*)(nb + sp[t]) = pre[t];
        }
        __syncthreads();
        buf ^= 1;
    }

    // epilogue: c frag mapping -> (w, m); float2 stores
    float* Yb = g_Y[yi];
    const int rr = w0 + wr * 32 + (lane >> 2);
    const int cc = m0 + wc * 32 + (lane & 3) * 2;
#pragma unroll
    for (int i = 0; i < 2; ++i)
#pragma unroll
        for (int j = 0; j < 4; ++j) {
            int w = rr + i * 16;
            int m = cc + j * 8;
            *(float2*)(Yb + (size_t)w * MCOLS + m) =
                make_float2(c[i][j][0], c[i][j][1]);
            *(float2*)(Yb + (size_t)(w + 8) * MCOLS + m) =
                make_float2(c[i][j][2], c[i][j][3]);
        }
}

// ---------------- 5) mix GEMM: out = W*[x;Y] + b (R11-proven, 316us) --------
__global__ void __launch_bounds__(256, 2) mix_gemm(
    const float* __restrict__ x, const float* __restrict__ Wm,
    const float* __restrict__ bias, float* __restrict__ out)
{
    const int bid = blockIdx.x;
    const int n   = bid / 26;
    const int m0  = (bid - n * 26) * 256;

    __shared__ __align__(16) float Ws[2][EBK][CO];
    __shared__ __align__(16) float Bs[2][EBK][256];

    const int tid = threadIdx.x;
    const int ty  = tid >> 5;
    const int tx  = tid & 31;
    const int wo_ = tid & 63;
    const int wk_ = tid >> 6;

    const int v_lo = m0 / 13;
    const int r0   = m0 - v_lo * 13;

    unsigned long long acc[4][8];
#pragma unroll
    for (int i = 0; i < 4; ++i)
#pragma unroll
        for (int jj = 0; jj < 8; ++jj) acc[i][jj] = 0ull;

    float4 pb[3];
    float  pw0, pw1;

    auto prefetch = [&](int jc) {
        const int j  = jc >> 2;
        const int c0 = (jc & 3) * EBK;
        if (j == 0) {
            const float* base = x + ((size_t)(n * CN + c0)) * VLN + m0;
#pragma unroll
            for (int t = 0; t < 2; ++t) {
                int e  = tid + t * 256;
                int cr = e >> 6, ff = e & 63;
                pb[t] = *(const float4*)(base + (size_t)cr * VLN + ff * 4);
            }
        } else {
            const float* base = g_Y[j - 1] + n * 416 + c0 * LN;
#pragma unroll
            for (int t = 0; t < 3; ++t) {
                int e = tid + t * 256;
                if (e < 546) {
                    int vr = e / 26, ff = e - vr * 26;
                    if (v_lo + vr < VN)
                        pb[t] = *(const float4*)(base + (size_t)(v_lo + vr) * MCOLS
                                                      + ff * 4);
                }
            }
        }
        pw0 = Wm[wo_ * CCAT + j * CN + c0 + wk_];
        pw1 = Wm[wo_ * CCAT + j * CN + c0 + wk_ + 4];
    };

    auto stage = [&](int jc, int pbuf) {
        const int j = jc >> 2;
        if (j == 0) {
#pragma unroll
            for (int t = 0; t < 2; ++t) {
                int e  = tid + t * 256;
                int cr = e >> 6, ff = e & 63;
                *(float4*)&Bs[pbuf][cr][ff * 4] = pb[t];
            }
        } else {
#pragma unroll
            for (int t = 0; t < 3; ++t) {
                int e = tid + t * 256;
                if (e < 546) {
                    int vr = e / 26, ff = e - vr * 26;
                    if (v_lo + vr < VN) {
                        int cb = vr * 13 - r0;
                        float vals[4] = {pb[t].x, pb[t].y, pb[t].z, pb[t].w};
#pragma unroll
                        for (int i = 0; i < 4; ++i) {
                            int elem = ff * 4 + i;
                            int cr = elem / 13;
                            int l  = elem - cr * 13;
                            int col = cb + l;
                            if (col >= 0 && col < 256)
                                Bs[pbuf][cr][col] = vals[i];
                        }
                    }
                }
            }
        }
        Ws[pbuf][wk_][wo_]     = pw0;
        Ws[pbuf][wk_ + 4][wo_] = pw1;
    };

    prefetch(0);
    stage(0, 0);
    __syncthreads();

    int buf = 0;
#pragma unroll 1
    for (int jc = 0; jc < NCHUNK; ++jc) {
        const bool has_next = (jc + 1 < NCHUNK);
        if (has_next) prefetch(jc + 1);
#pragma unroll
        for (int kk = 0; kk < EBK; ++kk) {
            ulonglong2 a01 = *(const ulonglong2*)&Ws[buf][kk][ty * 4];
            ulonglong2 a23 = *(const ulonglong2*)&Ws[buf][kk][32 + ty * 4];
            float4 blo = *(const float4*)&Bs[buf][kk][tx * 4];
            float4 bhi = *(const float4*)&Bs[buf][kk][128 + tx * 4];
            unsigned long long av[4] = {a01.x, a01.y, a23.x, a23.y};
            unsigned long long bb[8];
            bb[0] = pack_dup(blo.x); bb[1] = pack_dup(blo.y);
            bb[2] = pack_dup(blo.z); bb[3] = pack_dup(blo.w);
            bb[4] = pack_dup(bhi.x); bb[5] = pack_dup(bhi.y);
            bb[6] = pack_dup(bhi.z); bb[7] = pack_dup(bhi.w);
#pragma unroll
            for (int i = 0; i < 4; ++i)
#pragma unroll
                for (int jj = 0; jj < 8; ++jj)
                    fma2(acc[i][jj], av[i], bb[jj]);
        }
        if (has_next) stage(jc + 1, buf ^ 1);
        __syncthreads();
        buf ^= 1;
    }

#pragma unroll
    for (int ia = 0; ia < 4; ++ia) {
        int o0 = ((ia >= 2) ? 32 : 0) + ty * 4 + (ia & 1) * 2;
        float blo = bias[o0], bhi = bias[o0 + 1];
        float* plo = out + ((size_t)n * CO + o0) * VLN + m0 + tx * 4;
        float* phi = plo + VLN;
        float4 vlo0 = make_float4(lo32(acc[ia][0]) + blo, lo32(acc[ia][1]) + blo,
                                  lo32(acc[ia][2]) + blo, lo32(acc[ia][3]) + blo);
        float4 vlo1 = make_float4(lo32(acc[ia][4]) + blo, lo32(acc[ia][5]) + blo,
                                  lo32(acc[ia][6]) + blo, lo32(acc[ia][7]) + blo);
        float4 vhi0 = make_float4(hi32(acc[ia][0]) + bhi, hi32(acc[ia][1]) + bhi,
                                  hi32(acc[ia][2]) + bhi, hi32(acc[ia][3]) + bhi);
        float4 vhi1 = make_float4(hi32(acc[ia][4]) + bhi, hi32(acc[ia][5]) + bhi,
                                  hi32(acc[ia][6]) + bhi, hi32(acc[ia][7]) + bhi);
        *(float4*)(plo)       = vlo0;
        *(float4*)(plo + 128) = vlo1;
        *(float4*)(phi)       = vhi0;
        *(float4*)(phi + 128) = vhi1;
    }
}

// ---------------- launch ----------------
extern "C" void kernel_launch(void* const* d_in, const int* in_sizes, int n_in,
                              void* d_out, int out_size) {
    (void)in_sizes; (void)n_in; (void)out_size;
    const float* x  = (const float*)d_in[0];
    const float* s0 = (const float*)d_in[1];
    const float* s1 = (const float*)d_in[2];
    const float* s2 = (const float*)d_in[3];
    const float* Wm = (const float*)d_in[4];
    const float* bb = (const float*)d_in[5];
    float* out = (float*)d_out;

    // 1) S2 = A*A (fp32)
    square_support<<<dim3(VN/64, VN/64, 3), 256>>>(s0, s1, s2);
    // 2) transposed bf16 hi/lo operands for 3 supports + 3 S2
    trans_split<<<dim3(16, 16, 6), 256>>>(s0, s1, s2);
    // 3) x -> XtT[m][v] bf16 hi/lo
    conv_xtT<<<NC, 256>>>(x);
    // 4) all 6 propagations on tensor cores (mma.sync bf16, 3-pass) -> g_Y
    mma_prop<<<dim3(MCOLS/128, VN/128, 6), 512>>>();
    // 5) mix GEMM (unchanged, proven)
    mix_gemm<<<dim3(BB * 26), 256>>>(x, Wm, bb, out);
}